// round 14
// baseline (speedup 1.0000x reference)
#include <cuda_runtime.h>
#include <math.h>

#define BATCH 128
#define N 256
#define NT 128
#define NP1 (N + 1)
#define NUM_CLASSES 8
#define CE_COEFF 10.0f
#define UNCLAIMED 0x7FFFFFFF
#define BIGF 1e30f
#define VMASK 0xFFFFFF00u
#define RR_PASSES 2

__device__ float g_batch_loss[BATCH];

__device__ __forceinline__ float fsqrt_approx(float x) {
    float r;
    asm("sqrt.approx.f32 %0, %1;" : "=f"(r) : "f"(x));
    return r;
}
__device__ __forceinline__ unsigned umin2(unsigned a, unsigned b) { return a < b ? a : b; }
__device__ __forceinline__ unsigned umax2(unsigned a, unsigned b) { return a > b ? a : b; }

__device__ __forceinline__ void sts_vol_v2(unsigned addr, unsigned v, unsigned stamp) {
    asm volatile("st.volatile.shared.v2.u32 [%0], {%1, %2};"
                 :: "r"(addr), "r"(v), "r"(stamp) : "memory");
}
__device__ __forceinline__ uint2 lds_vol_v2(unsigned addr) {
    uint2 r;
    asm volatile("ld.volatile.shared.v2.u32 {%0, %1}, [%2];"
                 : "=r"(r.x), "=r"(r.y) : "r"(addr) : "memory");
    return r;
}

// One CTA per batch, 128 threads (4 warps), thread tid owns columns tid, tid+128.
// R8/R13 structure with the per-step __syncthreads replaced by stamped
// volatile spin-flags (parity double-buffered, monotone stamps).
__global__ __launch_bounds__(NT, 1) void hungarian_loss_kernel(
    const float* __restrict__ set1,   // [B, N, 3]
    const float* __restrict__ set2)   // [B, N, 10]
{
    const int b    = blockIdx.x;
    const int tid  = threadIdx.x;
    const int lane = tid & 31;
    const int wid  = tid >> 5;
    const int j0c  = tid + 1;          // 1-based column ids
    const int j1c  = tid + 129;

    __shared__ float s1x[N], s1y[N], s1l[N];
    __shared__ float s2x[N], s2y[N];
    __shared__ float u[NP1];
    __shared__ __align__(16) float4 rowdat[NP1]; // per column j: {x,y,u,row} of p[j]
    __shared__ int   way[NP1];
    __shared__ int   rowclaim[N];
    __shared__ int   listA[N], listB[N];
    __shared__ unsigned warpmask[8];
    __shared__ int   snfree, snext;
    __shared__ __align__(16) unsigned red1[2][4];
    __shared__ __align__(16) unsigned red2s[2][4];
    __shared__ __align__(16) unsigned pub[2][4][2];  // [parity][warp]{value,stamp}
    __shared__ float swsum[4];

    const float* s1p = set1 + (size_t)b * N * 3;
    const float* s2p = set2 + (size_t)b * N * 10;

    #pragma unroll
    for (int q = 0; q < 2; ++q) {
        const int e = tid + q * NT;
        s1x[e] = s1p[e * 3 + 0];
        s1y[e] = s1p[e * 3 + 1];
        s1l[e] = s1p[e * 3 + 2];
        s2x[e] = s2p[e * 10 + 0];
        s2y[e] = s2p[e * 10 + 1];
        u[e]   = 0.0f;
        rowdat[e + 1] = make_float4(0.f, 0.f, 0.f, __int_as_float(0));
        rowclaim[e]   = UNCLAIMED;
    }
    if (tid == 0) { u[N] = 0.0f; rowdat[0] = make_float4(0.f, 0.f, 0.f, __int_as_float(0)); }
    if (tid < 8) { pub[tid >> 2][tid & 3][0] = 0xFFFFFFFFu; pub[tid >> 2][tid & 3][1] = 0u; }
    __syncthreads();

    const float cx0 = s2x[tid],       cy0 = s2y[tid];
    const float cx1 = s2x[tid + NT],  cy1 = s2y[tid + NT];
    float v0, v1;                     // column duals, register-resident

    // ---- Phase 1: column reduction ----
    {
        float bd0 = BIGF, bd1 = BIGF;
        int   bi0 = 0,    bi1 = 0;
        #pragma unroll 4
        for (int i = 0; i < N; ++i) {
            const float sx = s1x[i], sy = s1y[i];
            const float dx0 = sx - cx0, dy0 = sy - cy0;
            const float d20 = fmaf(dx0, dx0, dy0 * dy0);
            if (d20 < bd0) { bd0 = d20; bi0 = i; }
            const float dx1 = sx - cx1, dy1 = sy - cy1;
            const float d21 = fmaf(dx1, dx1, dy1 * dy1);
            if (d21 < bd1) { bd1 = d21; bi1 = i; }
        }
        v0 = fsqrt_approx(fmaxf(bd0, 0.0f));
        v1 = fsqrt_approx(fmaxf(bd1, 0.0f));
        atomicMin(&rowclaim[bi0], tid);
        atomicMin(&rowclaim[bi1], tid + NT);
        __syncthreads();
        if (rowclaim[bi0] == tid)
            rowdat[j0c] = make_float4(s1x[bi0], s1y[bi0], 0.0f, __int_as_float(bi0 + 1));
        if (rowclaim[bi1] == tid + NT)
            rowdat[j1c] = make_float4(s1x[bi1], s1y[bi1], 0.0f, __int_as_float(bi1 + 1));
        const bool f0 = (rowclaim[tid] == UNCLAIMED);
        const bool f1 = (rowclaim[tid + NT] == UNCLAIMED);
        const unsigned wm0 = __ballot_sync(0xffffffffu, f0);
        const unsigned wm1 = __ballot_sync(0xffffffffu, f1);
        if (lane == 0) { warpmask[wid] = wm0; warpmask[wid + 4] = wm1; }
        __syncthreads();
        int base0 = 0, base1 = 0, tot = 0;
        #pragma unroll
        for (int w = 0; w < 8; ++w) {
            const int c = __popc(warpmask[w]);
            if (w < wid)     base0 += c;
            if (w < wid + 4) base1 += c;
            tot += c;
        }
        const unsigned lm = (1u << lane) - 1u;
        if (f0) listA[base0 + __popc(wm0 & lm)] = tid + 1;
        if (f1) listA[base1 + __popc(wm1 & lm)] = tid + NT + 1;
        if (tid == 0) snfree = tot;
        __syncthreads();
    }

    // ---- Phase 1.5: augmenting row reduction (2 passes) ----
    int ncur = snfree;
    {
        int par = 0;
        for (int run = 0; run < RR_PASSES; ++run) {
            int* cur = ((run & 1) == 0) ? listA : listB;
            int* nxt = ((run & 1) == 0) ? listB : listA;
            if (tid == 0) snext = 0;
            __syncthreads();
            for (int t = 0; t < ncur; ++t) {
                const int i = cur[t];
                const float sx = s1x[i - 1], sy = s1y[i - 1];
                const float dx0 = sx - cx0, dy0 = sy - cy0;
                const float rc0 = fmaxf(fsqrt_approx(fmaf(dx0, dx0, dy0 * dy0)) - v0, 0.0f);
                const float dx1 = sx - cx1, dy1 = sy - cy1;
                const float rc1 = fmaxf(fsqrt_approx(fmaf(dx1, dx1, dy1 * dy1)) - v1, 0.0f);
                const unsigned b0 = (__float_as_uint(rc0) & VMASK) | (unsigned)tid;
                const unsigned b1 = (__float_as_uint(rc1) & VMASK) | (unsigned)(tid + NT);
                const unsigned bmin = umin2(b0, b1);
                const unsigned bmax = umax2(b0, b1);
                const unsigned m1w  = __reduce_min_sync(0xffffffffu, bmin);
                const unsigned b2   = (bmin == m1w) ? bmax : bmin;
                const unsigned m2w  = __reduce_min_sync(0xffffffffu, b2);
                if (lane == 0) { red1[par][wid] = m1w; red2s[par][wid] = m2w; }
                __syncthreads();
                const uint4 r1 = *(const uint4*)&red1[par][0];
                const unsigned bp = umin2(umin2(r1.x, r1.y), umin2(r1.z, r1.w));
                const uint4 r2 = *(const uint4*)&red2s[par][0];
                unsigned sec = 0xFFFFFFFFu;
                sec = umin2(sec, (r1.x == bp) ? r2.x : r1.x);
                sec = umin2(sec, (r1.y == bp) ? r2.y : r1.y);
                sec = umin2(sec, (r1.z == bp) ? r2.z : r1.z);
                sec = umin2(sec, (r1.w == bp) ? r2.w : r1.w);
                const int   jone = (int)(bp & 0xFFu) + 1;
                const float m1   = __uint_as_float(bp & VMASK);
                const float m2   = __uint_as_float(sec & VMASK);
                if (tid == ((jone - 1) & (NT - 1))) {   // owner thread
                    const int k = __float_as_int(rowdat[jone].w);
                    if (m1 < m2) {
                        if (jone - 1 < NT) v0 -= (m2 - m1); else v1 -= (m2 - m1);
                        rowdat[jone] = make_float4(sx, sy, m2, __int_as_float(i));
                        u[i] = m2;
                        if (k != 0) { nxt[snext] = k; snext = snext + 1; }
                    } else {
                        if (k == 0) {
                            rowdat[jone] = make_float4(sx, sy, m2, __int_as_float(i));
                            u[i] = m2;
                        } else { nxt[snext] = i; snext = snext + 1; }
                    }
                }
                par ^= 1;
            }
            __syncthreads();
            ncur = snext;
            __syncthreads();
        }
    }
    // remaining free rows now in listA[0..ncur)

    const unsigned pub_base = (unsigned)__cvta_generic_to_shared(&pub[0][0][0]);
    unsigned s_step = 1;               // monotone stamp, never reset

    // ---- Phase 2: augmenting paths, branchless, spin-flag synchronized ----
    for (int idx = 0; idx < ncur; ++idx) {
        const int ifree = listA[idx];

        unsigned db0 = 0xFFFFFFFFu, db1 = 0xFFFFFFFFu;
        int   way0 = 0, way1 = 0;
        bool  used0 = false, used1 = false;

        int   jprev = 0;
        int   jfin;
        float rx   = s1x[ifree - 1];
        float ry   = s1y[ifree - 1];
        float u0   = u[ifree];
        float D    = 0.0f;

        while (true) {
            const float base = D - u0;
            const float dx0 = rx - cx0, dy0 = ry - cy0;
            const float c0  = fsqrt_approx(fmaf(dx0, dx0, dy0 * dy0));
            const float cand0 = fmaxf(base + (c0 - v0), D);
            const float dx1 = rx - cx1, dy1 = ry - cy1;
            const float c1  = fsqrt_approx(fmaf(dx1, dx1, dy1 * dy1));
            const float cand1 = fmaxf(base + (c1 - v1), D);

            const unsigned cb0 = (__float_as_uint(cand0) & VMASK) | (unsigned)tid;
            const bool be0 = (cb0 < db0) & (!used0);
            db0  = be0 ? cb0  : db0;
            way0 = be0 ? jprev : way0;
            const unsigned cb1 = (__float_as_uint(cand1) & VMASK) | (unsigned)(tid + NT);
            const bool be1 = (cb1 < db1) & (!used1);
            db1  = be1 ? cb1  : db1;
            way1 = be1 ? jprev : way1;

            const unsigned my0 = used0 ? 0xFFFFFFFFu : db0;
            const unsigned my1 = used1 ? 0xFFFFFFFFu : db1;
            const unsigned m = __reduce_min_sync(0xffffffffu, umin2(my0, my1));

            // publish {min, stamp} (single 8B volatile store: no tearing)
            const unsigned slot = pub_base + (s_step & 1u) * 32u;
            if (lane == 0) sts_vol_v2(slot + wid * 8u, m, s_step);

            // spin until all 4 warp stamps reach s_step
            unsigned best;
            for (;;) {
                const uint2 a0 = lds_vol_v2(slot +  0u);
                const uint2 a1 = lds_vol_v2(slot +  8u);
                const uint2 a2 = lds_vol_v2(slot + 16u);
                const uint2 a3 = lds_vol_v2(slot + 24u);
                if (((a0.y ^ s_step) | (a1.y ^ s_step) |
                     (a2.y ^ s_step) | (a3.y ^ s_step)) == 0u) {
                    best = umin2(umin2(a0.x, a1.x), umin2(a2.x, a3.x));
                    break;
                }
            }
            s_step++;

            D = __uint_as_float(best & VMASK);
            const int jz = (int)(best & 0xFFu);
            const int jn = jz + 1;

            const float4 rd = rowdat[jn];
            const int pj = __float_as_int(rd.w);
            if (pj == 0) { jfin = jn; break; }   // uniform branch

            used0 |= (jz == tid);
            used1 |= (jz == tid + NT);

            jprev = jn;
            rx = rd.x;
            ry = rd.y;
            u0 = rd.z;
        }

        way[j0c] = way0;
        way[j1c] = way1;
        // deferred dual updates: dmark = frozen settled dist, prow = p[j]
        if (used0) {
            const float dmark = __uint_as_float(db0 & VMASK);
            const int   prow  = __float_as_int(rowdat[j0c].w);
            const float diff  = D - dmark;
            v0 -= diff;
            u[prow] += diff;
            rowdat[j0c].z += diff;
        }
        if (used1) {
            const float dmark = __uint_as_float(db1 & VMASK);
            const int   prow  = __float_as_int(rowdat[j1c].w);
            const float diff  = D - dmark;
            v1 -= diff;
            u[prow] += diff;
            rowdat[j1c].z += diff;
        }
        if (tid == 0) u[ifree] += D;
        __syncthreads();
        if (tid == 0) {
            int jj = jfin;
            while (jj != 0) {
                const int jp = way[jj];
                if (jp == 0) {
                    rowdat[jj] = make_float4(s1x[ifree - 1], s1y[ifree - 1],
                                             u[ifree], __int_as_float(ifree));
                } else {
                    rowdat[jj] = rowdat[jp];
                }
                jj = jp;
            }
        }
        __syncthreads();
    }

    // ---- Phase 3: loss epilogue, 2 columns per thread ----
    float mds = 0.0f, nlls = 0.0f, cnts = 0.0f;
    #pragma unroll
    for (int q = 0; q < 2; ++q) {
        const int col = tid + q * NT;
        const float4 rdf = rowdat[col + 1];
        const int r = __float_as_int(rdf.w) - 1;

        const float dxm = rdf.x - s2x[col];
        const float dym = rdf.y - s2y[col];
        mds += fsqrt_approx(fmaxf(fmaf(dxm, dxm, dym * dym), 0.0f));

        float lg[NUM_CLASSES];
        float mx = -1e30f;
        #pragma unroll
        for (int k = 0; k < NUM_CLASSES; ++k) {
            lg[k] = s2p[col * 10 + 2 + k];
            mx = fmaxf(mx, lg[k]);
        }
        float se = 0.0f;
        #pragma unroll
        for (int k = 0; k < NUM_CLASSES; ++k) se += expf(lg[k] - mx);
        const float lse = mx + logf(se);

        const int  t    = (int)s1l[r];
        const bool mask = (t != -1);
        const int  st   = mask ? ((t < 0) ? 0 : (t >= NUM_CLASSES ? NUM_CLASSES - 1 : t)) : 0;
        nlls += mask ? (lse - lg[st]) : 0.0f;
        cnts += mask ? 1.0f : 0.0f;
    }

    float sv[3] = { mds, nlls, cnts };
    #pragma unroll
    for (int q = 0; q < 3; ++q) {
        float vv = sv[q];
        #pragma unroll
        for (int off = 16; off > 0; off >>= 1)
            vv += __shfl_down_sync(0xffffffffu, vv, off);
        if (lane == 0) swsum[wid] = vv;
        __syncthreads();
        if (tid == 0) sv[q] = swsum[0] + swsum[1] + swsum[2] + swsum[3];
        __syncthreads();
    }

    if (tid == 0) {
        const float loss1 = sv[0] / (float)N;
        const float denom = fmaxf(sv[2], 1.0f);
        const float loss2 = CE_COEFF * (sv[1] / denom);
        g_batch_loss[b] = loss1 + loss2;
    }
}

__global__ void finalize_kernel(float* __restrict__ out) {
    __shared__ float s[BATCH];
    const int t = threadIdx.x;
    s[t] = g_batch_loss[t];
    __syncthreads();
    #pragma unroll
    for (int off = BATCH / 2; off > 0; off >>= 1) {
        if (t < off) s[t] += s[t + off];
        __syncthreads();
    }
    if (t == 0) out[0] = s[0];
}

extern "C" void kernel_launch(void* const* d_in, const int* in_sizes, int n_in,
                              void* d_out, int out_size) {
    (void)in_sizes; (void)n_in; (void)out_size;
    const float* set1 = (const float*)d_in[0];
    const float* set2 = (const float*)d_in[1];
    float* out = (float*)d_out;

    hungarian_loss_kernel<<<BATCH, NT>>>(set1, set2);
    finalize_kernel<<<1, BATCH>>>(out);
}

// round 15
// speedup vs baseline: 1.1353x; 1.1353x over previous
#include <cuda_runtime.h>
#include <math.h>

#define BATCH 128
#define N 256
#define NT 128
#define NP1 (N + 1)
#define NUM_CLASSES 8
#define CE_COEFF 10.0f
#define UNCLAIMED 0x7FFFFFFF
#define BIGF 1e30f
#define VMASK 0xFFFFFF00u
#define RR_PASSES 2

__device__ float g_batch_loss[BATCH];

__device__ __forceinline__ float fsqrt_approx(float x) {
    float r;
    asm("sqrt.approx.f32 %0, %1;" : "=f"(r) : "f"(x));
    return r;
}
__device__ __forceinline__ unsigned umin2(unsigned a, unsigned b) { return a < b ? a : b; }
__device__ __forceinline__ unsigned umax2(unsigned a, unsigned b) { return a > b ? a : b; }

// One CTA per batch, 128 threads (4 warps), thread tid owns columns tid, tid+128.
// R8/R13 structure (measured optimum). Single barrier per augmentation tail:
// the chain-walk's writes are ordered by the NEXT Dijkstra's in-loop barrier
// (pre-barrier code reads only constants/registers/u[ifree], none touched here).
__global__ __launch_bounds__(NT, 1) void hungarian_loss_kernel(
    const float* __restrict__ set1,   // [B, N, 3]
    const float* __restrict__ set2)   // [B, N, 10]
{
    const int b    = blockIdx.x;
    const int tid  = threadIdx.x;
    const int lane = tid & 31;
    const int wid  = tid >> 5;
    const int j0c  = tid + 1;          // 1-based column ids
    const int j1c  = tid + 129;

    __shared__ float s1x[N], s1y[N], s1l[N];
    __shared__ float s2x[N], s2y[N];
    __shared__ float u[NP1];
    __shared__ __align__(16) float4 rowdat[NP1]; // per column j: {x,y,u,row} of p[j]
    __shared__ int   way[NP1];
    __shared__ int   rowclaim[N];
    __shared__ int   listA[N], listB[N];
    __shared__ unsigned warpmask[8];
    __shared__ int   snfree, snext;
    __shared__ __align__(16) unsigned red1[2][4];
    __shared__ __align__(16) unsigned red2s[2][4];
    __shared__ float swsum[4];

    const float* s1p = set1 + (size_t)b * N * 3;
    const float* s2p = set2 + (size_t)b * N * 10;

    #pragma unroll
    for (int q = 0; q < 2; ++q) {
        const int e = tid + q * NT;
        s1x[e] = s1p[e * 3 + 0];
        s1y[e] = s1p[e * 3 + 1];
        s1l[e] = s1p[e * 3 + 2];
        s2x[e] = s2p[e * 10 + 0];
        s2y[e] = s2p[e * 10 + 1];
        u[e]   = 0.0f;
        rowdat[e + 1] = make_float4(0.f, 0.f, 0.f, __int_as_float(0));
        rowclaim[e]   = UNCLAIMED;
    }
    if (tid == 0) { u[N] = 0.0f; rowdat[0] = make_float4(0.f, 0.f, 0.f, __int_as_float(0)); }
    __syncthreads();

    const float cx0 = s2x[tid],       cy0 = s2y[tid];
    const float cx1 = s2x[tid + NT],  cy1 = s2y[tid + NT];
    float v0, v1;                     // column duals, register-resident

    // ---- Phase 1: column reduction ----
    {
        float bd0 = BIGF, bd1 = BIGF;
        int   bi0 = 0,    bi1 = 0;
        #pragma unroll 4
        for (int i = 0; i < N; ++i) {
            const float sx = s1x[i], sy = s1y[i];
            const float dx0 = sx - cx0, dy0 = sy - cy0;
            const float d20 = fmaf(dx0, dx0, dy0 * dy0);
            if (d20 < bd0) { bd0 = d20; bi0 = i; }
            const float dx1 = sx - cx1, dy1 = sy - cy1;
            const float d21 = fmaf(dx1, dx1, dy1 * dy1);
            if (d21 < bd1) { bd1 = d21; bi1 = i; }
        }
        v0 = fsqrt_approx(fmaxf(bd0, 0.0f));
        v1 = fsqrt_approx(fmaxf(bd1, 0.0f));
        atomicMin(&rowclaim[bi0], tid);
        atomicMin(&rowclaim[bi1], tid + NT);
        __syncthreads();
        if (rowclaim[bi0] == tid)
            rowdat[j0c] = make_float4(s1x[bi0], s1y[bi0], 0.0f, __int_as_float(bi0 + 1));
        if (rowclaim[bi1] == tid + NT)
            rowdat[j1c] = make_float4(s1x[bi1], s1y[bi1], 0.0f, __int_as_float(bi1 + 1));
        const bool f0 = (rowclaim[tid] == UNCLAIMED);
        const bool f1 = (rowclaim[tid + NT] == UNCLAIMED);
        const unsigned wm0 = __ballot_sync(0xffffffffu, f0);
        const unsigned wm1 = __ballot_sync(0xffffffffu, f1);
        if (lane == 0) { warpmask[wid] = wm0; warpmask[wid + 4] = wm1; }
        __syncthreads();
        int base0 = 0, base1 = 0, tot = 0;
        #pragma unroll
        for (int w = 0; w < 8; ++w) {
            const int c = __popc(warpmask[w]);
            if (w < wid)     base0 += c;
            if (w < wid + 4) base1 += c;
            tot += c;
        }
        const unsigned lm = (1u << lane) - 1u;
        if (f0) listA[base0 + __popc(wm0 & lm)] = tid + 1;
        if (f1) listA[base1 + __popc(wm1 & lm)] = tid + NT + 1;
        if (tid == 0) snfree = tot;
        __syncthreads();
    }

    // ---- Phase 1.5: augmenting row reduction (2 passes) ----
    int ncur = snfree;
    {
        int par = 0;
        for (int run = 0; run < RR_PASSES; ++run) {
            int* cur = ((run & 1) == 0) ? listA : listB;
            int* nxt = ((run & 1) == 0) ? listB : listA;
            if (tid == 0) snext = 0;
            __syncthreads();
            for (int t = 0; t < ncur; ++t) {
                const int i = cur[t];
                const float sx = s1x[i - 1], sy = s1y[i - 1];
                const float dx0 = sx - cx0, dy0 = sy - cy0;
                const float rc0 = fmaxf(fsqrt_approx(fmaf(dx0, dx0, dy0 * dy0)) - v0, 0.0f);
                const float dx1 = sx - cx1, dy1 = sy - cy1;
                const float rc1 = fmaxf(fsqrt_approx(fmaf(dx1, dx1, dy1 * dy1)) - v1, 0.0f);
                const unsigned b0 = (__float_as_uint(rc0) & VMASK) | (unsigned)tid;
                const unsigned b1 = (__float_as_uint(rc1) & VMASK) | (unsigned)(tid + NT);
                const unsigned bmin = umin2(b0, b1);
                const unsigned bmax = umax2(b0, b1);
                const unsigned m1w  = __reduce_min_sync(0xffffffffu, bmin);
                const unsigned b2   = (bmin == m1w) ? bmax : bmin;
                const unsigned m2w  = __reduce_min_sync(0xffffffffu, b2);
                if (lane == 0) { red1[par][wid] = m1w; red2s[par][wid] = m2w; }
                __syncthreads();
                const uint4 r1 = *(const uint4*)&red1[par][0];
                const unsigned bp = umin2(umin2(r1.x, r1.y), umin2(r1.z, r1.w));
                const uint4 r2 = *(const uint4*)&red2s[par][0];
                unsigned sec = 0xFFFFFFFFu;
                sec = umin2(sec, (r1.x == bp) ? r2.x : r1.x);
                sec = umin2(sec, (r1.y == bp) ? r2.y : r1.y);
                sec = umin2(sec, (r1.z == bp) ? r2.z : r1.z);
                sec = umin2(sec, (r1.w == bp) ? r2.w : r1.w);
                const int   jone = (int)(bp & 0xFFu) + 1;
                const float m1   = __uint_as_float(bp & VMASK);
                const float m2   = __uint_as_float(sec & VMASK);
                if (tid == ((jone - 1) & (NT - 1))) {   // owner thread
                    const int k = __float_as_int(rowdat[jone].w);
                    if (m1 < m2) {
                        if (jone - 1 < NT) v0 -= (m2 - m1); else v1 -= (m2 - m1);
                        rowdat[jone] = make_float4(sx, sy, m2, __int_as_float(i));
                        u[i] = m2;
                        if (k != 0) { nxt[snext] = k; snext = snext + 1; }
                    } else {
                        if (k == 0) {
                            rowdat[jone] = make_float4(sx, sy, m2, __int_as_float(i));
                            u[i] = m2;
                        } else { nxt[snext] = i; snext = snext + 1; }
                    }
                }
                par ^= 1;
            }
            __syncthreads();
            ncur = snext;
            __syncthreads();
        }
    }
    // remaining free rows now in listA[0..ncur)

    // ---- Phase 2: augmenting paths, branchless inner loop ----
    for (int idx = 0; idx < ncur; ++idx) {
        const int ifree = listA[idx];

        unsigned db0 = 0xFFFFFFFFu, db1 = 0xFFFFFFFFu;
        int   way0 = 0, way1 = 0;
        bool  used0 = false, used1 = false;

        int   jprev = 0;
        int   jfin;
        float rx   = s1x[ifree - 1];
        float ry   = s1y[ifree - 1];
        float u0   = u[ifree];          // free rows never updated during phase 2
        float D    = 0.0f;
        int   par  = 0;

        while (true) {
            const float base = D - u0;
            const float dx0 = rx - cx0, dy0 = ry - cy0;
            const float c0  = fsqrt_approx(fmaf(dx0, dx0, dy0 * dy0));
            const float cand0 = fmaxf(base + (c0 - v0), D);
            const float dx1 = rx - cx1, dy1 = ry - cy1;
            const float c1  = fsqrt_approx(fmaf(dx1, dx1, dy1 * dy1));
            const float cand1 = fmaxf(base + (c1 - v1), D);

            const unsigned cb0 = (__float_as_uint(cand0) & VMASK) | (unsigned)tid;
            const bool be0 = (cb0 < db0) & (!used0);
            db0  = be0 ? cb0  : db0;
            way0 = be0 ? jprev : way0;
            const unsigned cb1 = (__float_as_uint(cand1) & VMASK) | (unsigned)(tid + NT);
            const bool be1 = (cb1 < db1) & (!used1);
            db1  = be1 ? cb1  : db1;
            way1 = be1 ? jprev : way1;

            const unsigned my0 = used0 ? 0xFFFFFFFFu : db0;
            const unsigned my1 = used1 ? 0xFFFFFFFFu : db1;
            const unsigned m = __reduce_min_sync(0xffffffffu, umin2(my0, my1));
            if (lane == 0) red1[par][wid] = m;
            __syncthreads();           // also orders prior chain-walk writes

            const uint4 r1 = *(const uint4*)&red1[par][0];
            const unsigned best = umin2(umin2(r1.x, r1.y), umin2(r1.z, r1.w));
            D = __uint_as_float(best & VMASK);
            const int jz = (int)(best & 0xFFu);
            const int jn = jz + 1;

            const float4 rd = rowdat[jn];
            const int pj = __float_as_int(rd.w);
            if (pj == 0) { jfin = jn; break; }   // uniform branch

            used0 |= (jz == tid);
            used1 |= (jz == tid + NT);

            jprev = jn;
            rx = rd.x;
            ry = rd.y;
            u0 = rd.z;
            par ^= 1;
        }

        way[j0c] = way0;
        way[j1c] = way1;
        // deferred dual updates: dmark = frozen settled dist, prow = p[j]
        if (used0) {
            const float dmark = __uint_as_float(db0 & VMASK);
            const int   prow  = __float_as_int(rowdat[j0c].w);
            const float diff  = D - dmark;
            v0 -= diff;
            u[prow] += diff;
            rowdat[j0c].z += diff;
        }
        if (used1) {
            const float dmark = __uint_as_float(db1 & VMASK);
            const int   prow  = __float_as_int(rowdat[j1c].w);
            const float diff  = D - dmark;
            v1 -= diff;
            u[prow] += diff;
            rowdat[j1c].z += diff;
        }
        if (tid == 0) u[ifree] += D;
        __syncthreads();                // order way/dual stores before chain walk
        if (tid == 0) {
            int jj = jfin;
            while (jj != 0) {
                const int jp = way[jj];
                if (jp == 0) {
                    rowdat[jj] = make_float4(s1x[ifree - 1], s1y[ifree - 1],
                                             u[ifree], __int_as_float(ifree));
                } else {
                    rowdat[jj] = rowdat[jp];
                }
                jj = jp;
            }
        }
        // NO trailing barrier: chain-walk writes are ordered by the next
        // Dijkstra's in-loop __syncthreads before anyone reads rowdat/red1.
    }
    __syncthreads();                    // final ordering before epilogue

    // ---- Phase 3: loss epilogue, 2 columns per thread ----
    float mds = 0.0f, nlls = 0.0f, cnts = 0.0f;
    #pragma unroll
    for (int q = 0; q < 2; ++q) {
        const int col = tid + q * NT;
        const float4 rdf = rowdat[col + 1];
        const int r = __float_as_int(rdf.w) - 1;

        const float dxm = rdf.x - s2x[col];
        const float dym = rdf.y - s2y[col];
        mds += fsqrt_approx(fmaxf(fmaf(dxm, dxm, dym * dym), 0.0f));

        float lg[NUM_CLASSES];
        float mx = -1e30f;
        #pragma unroll
        for (int k = 0; k < NUM_CLASSES; ++k) {
            lg[k] = s2p[col * 10 + 2 + k];
            mx = fmaxf(mx, lg[k]);
        }
        float se = 0.0f;
        #pragma unroll
        for (int k = 0; k < NUM_CLASSES; ++k) se += expf(lg[k] - mx);
        const float lse = mx + logf(se);

        const int  t    = (int)s1l[r];
        const bool mask = (t != -1);
        const int  st   = mask ? ((t < 0) ? 0 : (t >= NUM_CLASSES ? NUM_CLASSES - 1 : t)) : 0;
        nlls += mask ? (lse - lg[st]) : 0.0f;
        cnts += mask ? 1.0f : 0.0f;
    }

    float sv[3] = { mds, nlls, cnts };
    #pragma unroll
    for (int q = 0; q < 3; ++q) {
        float vv = sv[q];
        #pragma unroll
        for (int off = 16; off > 0; off >>= 1)
            vv += __shfl_down_sync(0xffffffffu, vv, off);
        if (lane == 0) swsum[wid] = vv;
        __syncthreads();
        if (tid == 0) sv[q] = swsum[0] + swsum[1] + swsum[2] + swsum[3];
        __syncthreads();
    }

    if (tid == 0) {
        const float loss1 = sv[0] / (float)N;
        const float denom = fmaxf(sv[2], 1.0f);
        const float loss2 = CE_COEFF * (sv[1] / denom);
        g_batch_loss[b] = loss1 + loss2;
    }
}

__global__ void finalize_kernel(float* __restrict__ out) {
    __shared__ float s[BATCH];
    const int t = threadIdx.x;
    s[t] = g_batch_loss[t];
    __syncthreads();
    #pragma unroll
    for (int off = BATCH / 2; off > 0; off >>= 1) {
        if (t < off) s[t] += s[t + off];
        __syncthreads();
    }
    if (t == 0) out[0] = s[0];
}

extern "C" void kernel_launch(void* const* d_in, const int* in_sizes, int n_in,
                              void* d_out, int out_size) {
    (void)in_sizes; (void)n_in; (void)out_size;
    const float* set1 = (const float*)d_in[0];
    const float* set2 = (const float*)d_in[1];
    float* out = (float*)d_out;

    hungarian_loss_kernel<<<BATCH, NT>>>(set1, set2);
    finalize_kernel<<<1, BATCH>>>(out);
}

// round 16
// speedup vs baseline: 1.1559x; 1.0181x over previous
#include <cuda_runtime.h>
#include <math.h>

#define BATCH 128
#define N 256
#define NT 128
#define NP1 (N + 1)
#define NUM_CLASSES 8
#define CE_COEFF 10.0f
#define UNCLAIMED 0x7FFFFFFF
#define BIGF 1e30f
#define VMASK 0xFFFFFF00u
#define RR_PASSES 2

__device__ float g_batch_loss[BATCH];

__device__ __forceinline__ float fsqrt_approx(float x) {
    float r;
    asm("sqrt.approx.f32 %0, %1;" : "=f"(r) : "f"(x));
    return r;
}
__device__ __forceinline__ unsigned umin2(unsigned a, unsigned b) { return a < b ? a : b; }
__device__ __forceinline__ unsigned umax2(unsigned a, unsigned b) { return a > b ? a : b; }

// One CTA per batch, 128 threads (4 warps), thread tid owns columns tid, tid+128.
// Champion configuration (R8): 4 warps x 2 cols/thread, 2 RR passes, branchless
// select-based marks, packed 24-bit dist + 8-bit col REDUX argmin, fused
// rowdat float4 table. Trailing per-augmentation barrier elided (proof: the
// chain-walk writes are ordered by the next Dijkstra's in-loop barrier; the
// pre-barrier section reads only registers and u[ifree], never written here).
__global__ __launch_bounds__(NT, 1) void hungarian_loss_kernel(
    const float* __restrict__ set1,   // [B, N, 3]
    const float* __restrict__ set2)   // [B, N, 10]
{
    const int b    = blockIdx.x;
    const int tid  = threadIdx.x;
    const int lane = tid & 31;
    const int wid  = tid >> 5;
    const int j0c  = tid + 1;          // 1-based column ids
    const int j1c  = tid + 129;

    __shared__ float s1x[N], s1y[N], s1l[N];
    __shared__ float s2x[N], s2y[N];
    __shared__ float u[NP1];
    __shared__ __align__(16) float4 rowdat[NP1]; // per column j: {x,y,u,row} of p[j]
    __shared__ int   way[NP1];
    __shared__ int   rowclaim[N];
    __shared__ int   listA[N], listB[N];
    __shared__ unsigned warpmask[8];
    __shared__ int   snfree, snext;
    __shared__ __align__(16) unsigned red1[2][4];
    __shared__ __align__(16) unsigned red2s[2][4];
    __shared__ float swsum[4];

    const float* s1p = set1 + (size_t)b * N * 3;
    const float* s2p = set2 + (size_t)b * N * 10;

    #pragma unroll
    for (int q = 0; q < 2; ++q) {
        const int e = tid + q * NT;
        s1x[e] = s1p[e * 3 + 0];
        s1y[e] = s1p[e * 3 + 1];
        s1l[e] = s1p[e * 3 + 2];
        s2x[e] = s2p[e * 10 + 0];
        s2y[e] = s2p[e * 10 + 1];
        u[e]   = 0.0f;
        rowdat[e + 1] = make_float4(0.f, 0.f, 0.f, __int_as_float(0));
        rowclaim[e]   = UNCLAIMED;
    }
    if (tid == 0) { u[N] = 0.0f; rowdat[0] = make_float4(0.f, 0.f, 0.f, __int_as_float(0)); }
    __syncthreads();

    const float cx0 = s2x[tid],       cy0 = s2y[tid];
    const float cx1 = s2x[tid + NT],  cy1 = s2y[tid + NT];
    float v0, v1;                     // column duals, register-resident

    // ---- Phase 1: column reduction ----
    {
        float bd0 = BIGF, bd1 = BIGF;
        int   bi0 = 0,    bi1 = 0;
        #pragma unroll 4
        for (int i = 0; i < N; ++i) {
            const float sx = s1x[i], sy = s1y[i];
            const float dx0 = sx - cx0, dy0 = sy - cy0;
            const float d20 = fmaf(dx0, dx0, dy0 * dy0);
            if (d20 < bd0) { bd0 = d20; bi0 = i; }
            const float dx1 = sx - cx1, dy1 = sy - cy1;
            const float d21 = fmaf(dx1, dx1, dy1 * dy1);
            if (d21 < bd1) { bd1 = d21; bi1 = i; }
        }
        v0 = fsqrt_approx(fmaxf(bd0, 0.0f));
        v1 = fsqrt_approx(fmaxf(bd1, 0.0f));
        atomicMin(&rowclaim[bi0], tid);
        atomicMin(&rowclaim[bi1], tid + NT);
        __syncthreads();
        if (rowclaim[bi0] == tid)
            rowdat[j0c] = make_float4(s1x[bi0], s1y[bi0], 0.0f, __int_as_float(bi0 + 1));
        if (rowclaim[bi1] == tid + NT)
            rowdat[j1c] = make_float4(s1x[bi1], s1y[bi1], 0.0f, __int_as_float(bi1 + 1));
        const bool f0 = (rowclaim[tid] == UNCLAIMED);
        const bool f1 = (rowclaim[tid + NT] == UNCLAIMED);
        const unsigned wm0 = __ballot_sync(0xffffffffu, f0);
        const unsigned wm1 = __ballot_sync(0xffffffffu, f1);
        if (lane == 0) { warpmask[wid] = wm0; warpmask[wid + 4] = wm1; }
        __syncthreads();
        int base0 = 0, base1 = 0, tot = 0;
        #pragma unroll
        for (int w = 0; w < 8; ++w) {
            const int c = __popc(warpmask[w]);
            if (w < wid)     base0 += c;
            if (w < wid + 4) base1 += c;
            tot += c;
        }
        const unsigned lm = (1u << lane) - 1u;
        if (f0) listA[base0 + __popc(wm0 & lm)] = tid + 1;
        if (f1) listA[base1 + __popc(wm1 & lm)] = tid + NT + 1;
        if (tid == 0) snfree = tot;
        __syncthreads();
    }

    // ---- Phase 1.5: augmenting row reduction (2 passes) ----
    int ncur = snfree;
    {
        int par = 0;
        for (int run = 0; run < RR_PASSES; ++run) {
            int* cur = ((run & 1) == 0) ? listA : listB;
            int* nxt = ((run & 1) == 0) ? listB : listA;
            if (tid == 0) snext = 0;
            __syncthreads();
            for (int t = 0; t < ncur; ++t) {
                const int i = cur[t];
                const float sx = s1x[i - 1], sy = s1y[i - 1];
                const float dx0 = sx - cx0, dy0 = sy - cy0;
                const float rc0 = fmaxf(fsqrt_approx(fmaf(dx0, dx0, dy0 * dy0)) - v0, 0.0f);
                const float dx1 = sx - cx1, dy1 = sy - cy1;
                const float rc1 = fmaxf(fsqrt_approx(fmaf(dx1, dx1, dy1 * dy1)) - v1, 0.0f);
                const unsigned b0 = (__float_as_uint(rc0) & VMASK) | (unsigned)tid;
                const unsigned b1 = (__float_as_uint(rc1) & VMASK) | (unsigned)(tid + NT);
                const unsigned bmin = umin2(b0, b1);
                const unsigned bmax = umax2(b0, b1);
                const unsigned m1w  = __reduce_min_sync(0xffffffffu, bmin);
                const unsigned b2   = (bmin == m1w) ? bmax : bmin;
                const unsigned m2w  = __reduce_min_sync(0xffffffffu, b2);
                if (lane == 0) { red1[par][wid] = m1w; red2s[par][wid] = m2w; }
                __syncthreads();
                const uint4 r1 = *(const uint4*)&red1[par][0];
                const unsigned bp = umin2(umin2(r1.x, r1.y), umin2(r1.z, r1.w));
                const uint4 r2 = *(const uint4*)&red2s[par][0];
                unsigned sec = 0xFFFFFFFFu;
                sec = umin2(sec, (r1.x == bp) ? r2.x : r1.x);
                sec = umin2(sec, (r1.y == bp) ? r2.y : r1.y);
                sec = umin2(sec, (r1.z == bp) ? r2.z : r1.z);
                sec = umin2(sec, (r1.w == bp) ? r2.w : r1.w);
                const int   jone = (int)(bp & 0xFFu) + 1;
                const float m1   = __uint_as_float(bp & VMASK);
                const float m2   = __uint_as_float(sec & VMASK);
                if (tid == ((jone - 1) & (NT - 1))) {   // owner thread
                    const int k = __float_as_int(rowdat[jone].w);
                    if (m1 < m2) {
                        if (jone - 1 < NT) v0 -= (m2 - m1); else v1 -= (m2 - m1);
                        rowdat[jone] = make_float4(sx, sy, m2, __int_as_float(i));
                        u[i] = m2;
                        if (k != 0) { nxt[snext] = k; snext = snext + 1; }
                    } else {
                        if (k == 0) {
                            rowdat[jone] = make_float4(sx, sy, m2, __int_as_float(i));
                            u[i] = m2;
                        } else { nxt[snext] = i; snext = snext + 1; }
                    }
                }
                par ^= 1;
            }
            __syncthreads();
            ncur = snext;
            __syncthreads();
        }
    }
    // remaining free rows now in listA[0..ncur)

    // ---- Phase 2: augmenting paths, branchless inner loop ----
    for (int idx = 0; idx < ncur; ++idx) {
        const int ifree = listA[idx];

        unsigned db0 = 0xFFFFFFFFu, db1 = 0xFFFFFFFFu;
        int   way0 = 0, way1 = 0;
        bool  used0 = false, used1 = false;
        float dm0 = 0.0f, dm1 = 0.0f;
        int   pr0 = 0, pr1 = 0;

        int   jcur = 0;
        int   jfin;
        int   i0   = ifree;
        float rx   = s1x[ifree - 1];
        float ry   = s1y[ifree - 1];
        float u0   = u[ifree];
        float D    = 0.0f;
        int   par  = 0;

        while (true) {
            const bool mk0 = (j0c == jcur);
            used0 |= mk0;  dm0 = mk0 ? D : dm0;  pr0 = mk0 ? i0 : pr0;
            const bool mk1 = (j1c == jcur);
            used1 |= mk1;  dm1 = mk1 ? D : dm1;  pr1 = mk1 ? i0 : pr1;

            const float base = D - u0;
            const float dx0 = rx - cx0, dy0 = ry - cy0;
            const float c0  = fsqrt_approx(fmaf(dx0, dx0, dy0 * dy0));
            const float cand0 = fmaxf(base + (c0 - v0), D);
            const float dx1 = rx - cx1, dy1 = ry - cy1;
            const float c1  = fsqrt_approx(fmaf(dx1, dx1, dy1 * dy1));
            const float cand1 = fmaxf(base + (c1 - v1), D);

            const unsigned cb0 = (__float_as_uint(cand0) & VMASK) | (unsigned)tid;
            const bool be0 = (cb0 < db0) & (!used0);
            db0  = be0 ? cb0  : db0;
            way0 = be0 ? jcur : way0;
            const unsigned cb1 = (__float_as_uint(cand1) & VMASK) | (unsigned)(tid + NT);
            const bool be1 = (cb1 < db1) & (!used1);
            db1  = be1 ? cb1  : db1;
            way1 = be1 ? jcur : way1;

            const unsigned my0 = used0 ? 0xFFFFFFFFu : db0;
            const unsigned my1 = used1 ? 0xFFFFFFFFu : db1;
            const unsigned m = __reduce_min_sync(0xffffffffu, umin2(my0, my1));
            if (lane == 0) red1[par][wid] = m;
            __syncthreads();            // also orders prior chain-walk writes

            const uint4 r1 = *(const uint4*)&red1[par][0];
            const unsigned best = umin2(umin2(r1.x, r1.y), umin2(r1.z, r1.w));
            D = __uint_as_float(best & VMASK);
            const int jn = (int)(best & 0xFFu) + 1;

            const float4 rd = rowdat[jn];
            const int pj = __float_as_int(rd.w);
            if (pj == 0) { jfin = jn; break; }   // uniform branch
            jcur = jn;
            i0   = pj;
            rx   = rd.x;
            ry   = rd.y;
            u0   = rd.z;
            par ^= 1;
        }

        way[j0c] = way0;
        way[j1c] = way1;
        if (used0) {
            const float diff = D - dm0;
            v0 -= diff;
            u[pr0] += diff;
            rowdat[j0c].z += diff;
        }
        if (used1) {
            const float diff = D - dm1;
            v1 -= diff;
            u[pr1] += diff;
            rowdat[j1c].z += diff;
        }
        if (tid == 0) u[ifree] += D;
        __syncthreads();                // order way/dual stores before chain walk
        if (tid == 0) {
            int jj = jfin;
            while (jj != 0) {
                const int jp = way[jj];
                if (jp == 0) {
                    rowdat[jj] = make_float4(s1x[ifree - 1], s1y[ifree - 1],
                                             u[ifree], __int_as_float(ifree));
                } else {
                    rowdat[jj] = rowdat[jp];
                }
                jj = jp;
            }
        }
        // trailing barrier elided: next in-loop __syncthreads orders these
        // writes before any rowdat/red1 read (pre-barrier code is register-only
        // plus u[ifree_new], which phase 2 never writes).
    }
    __syncthreads();                    // final ordering before epilogue

    // ---- Phase 3: loss epilogue, 2 columns per thread ----
    float mds = 0.0f, nlls = 0.0f, cnts = 0.0f;
    #pragma unroll
    for (int q = 0; q < 2; ++q) {
        const int col = tid + q * NT;
        const float4 rdf = rowdat[col + 1];
        const int r = __float_as_int(rdf.w) - 1;

        const float dxm = rdf.x - s2x[col];
        const float dym = rdf.y - s2y[col];
        mds += fsqrt_approx(fmaxf(fmaf(dxm, dxm, dym * dym), 0.0f));

        float lg[NUM_CLASSES];
        float mx = -1e30f;
        #pragma unroll
        for (int k = 0; k < NUM_CLASSES; ++k) {
            lg[k] = s2p[col * 10 + 2 + k];
            mx = fmaxf(mx, lg[k]);
        }
        float se = 0.0f;
        #pragma unroll
        for (int k = 0; k < NUM_CLASSES; ++k) se += expf(lg[k] - mx);
        const float lse = mx + logf(se);

        const int  t    = (int)s1l[r];
        const bool mask = (t != -1);
        const int  st   = mask ? ((t < 0) ? 0 : (t >= NUM_CLASSES ? NUM_CLASSES - 1 : t)) : 0;
        nlls += mask ? (lse - lg[st]) : 0.0f;
        cnts += mask ? 1.0f : 0.0f;
    }

    float sv[3] = { mds, nlls, cnts };
    #pragma unroll
    for (int q = 0; q < 3; ++q) {
        float vv = sv[q];
        #pragma unroll
        for (int off = 16; off > 0; off >>= 1)
            vv += __shfl_down_sync(0xffffffffu, vv, off);
        if (lane == 0) swsum[wid] = vv;
        __syncthreads();
        if (tid == 0) sv[q] = swsum[0] + swsum[1] + swsum[2] + swsum[3];
        __syncthreads();
    }

    if (tid == 0) {
        const float loss1 = sv[0] / (float)N;
        const float denom = fmaxf(sv[2], 1.0f);
        const float loss2 = CE_COEFF * (sv[1] / denom);
        g_batch_loss[b] = loss1 + loss2;
    }
}

__global__ void finalize_kernel(float* __restrict__ out) {
    __shared__ float s[BATCH];
    const int t = threadIdx.x;
    s[t] = g_batch_loss[t];
    __syncthreads();
    #pragma unroll
    for (int off = BATCH / 2; off > 0; off >>= 1) {
        if (t < off) s[t] += s[t + off];
        __syncthreads();
    }
    if (t == 0) out[0] = s[0];
}

extern "C" void kernel_launch(void* const* d_in, const int* in_sizes, int n_in,
                              void* d_out, int out_size) {
    (void)in_sizes; (void)n_in; (void)out_size;
    const float* set1 = (const float*)d_in[0];
    const float* set2 = (const float*)d_in[1];
    float* out = (float*)d_out;

    hungarian_loss_kernel<<<BATCH, NT>>>(set1, set2);
    finalize_kernel<<<1, BATCH>>>(out);
}